// round 2
// baseline (speedup 1.0000x reference)
#include <cuda_runtime.h>
#include <math.h>

static constexpr int NPTS = 500000;
static constexpr int NVOX = 1 << 24;   // 256^3

// Scratch: two complex 256^3 grids (128 MB each). Static __device__ arrays are
// the allowed scratch mechanism (no runtime allocation).
__device__ float2 gA[NVOX];   // holds ras_x + i*ras_y, then its forward FFT Z(k)
__device__ float2 gB[NVOX];   // holds ras_z (+ i*0), then W(k)=N^_z, then Phi(k), then ifft(Phi)
__device__ double g_accum;    // sum of interpolated phi at the input points

// ---------------------------------------------------------------------------
// helpers
// ---------------------------------------------------------------------------
__device__ __forceinline__ void corner_setup(float v, int& i0, int& i1, float& f) {
    float x  = v * 256.0f;        // exact (power-of-two scale)
    float fl = floorf(x);
    i0 = (int)fl;
    f  = x - fl;                  // exact fractional part
    i1 = (i0 + 1) & 255;          // wrapped upper corner
}

// ---------------------------------------------------------------------------
// 1) trilinear scatter-add of normals into gA (x,y) and gB (z)
// ---------------------------------------------------------------------------
__global__ void __launch_bounds__(256) scatter_kernel(const float* __restrict__ V,
                                                      const float* __restrict__ N) {
    int p = blockIdx.x * 256 + threadIdx.x;
    if (p >= NPTS) return;
    float vx = V[3 * p + 0], vy = V[3 * p + 1], vz = V[3 * p + 2];
    float nx = N[3 * p + 0], ny = N[3 * p + 1], nz = N[3 * p + 2];

    int ix0, ix1, iy0, iy1, iz0, iz1;
    float fx, fy, fz;
    corner_setup(vx, ix0, ix1, fx);
    corner_setup(vy, iy0, iy1, fy);
    corner_setup(vz, iz0, iz1, fz);

    float wx[2] = {1.0f - fx, fx};
    float wy[2] = {1.0f - fy, fy};
    float wz[2] = {1.0f - fz, fz};
    int ix[2] = {ix0, ix1}, iy[2] = {iy0, iy1}, iz[2] = {iz0, iz1};

#pragma unroll
    for (int c = 0; c < 8; c++) {
        int b0 = (c >> 2) & 1, b1 = (c >> 1) & 1, b2 = c & 1;
        int lin = (((ix[b0] << 8) | iy[b1]) << 8) | iz[b2];
        float w = wx[b0] * wy[b1] * wz[b2];
        atomicAdd(&gA[lin].x, w * nx);
        atomicAdd(&gA[lin].y, w * ny);
        atomicAdd(&gB[lin].x, w * nz);
    }
}

// ---------------------------------------------------------------------------
// 256-point radix-2 DIT FFT executed by one warp on shared memory.
// Input must be stored bit-reversed; output is natural order.
// RS = element stride (in floats index units) inside the smem buffers.
// ---------------------------------------------------------------------------
template <int RS>
__device__ __forceinline__ void warp_fft256(float* re, float* im, int lane,
                                            const float* twr, const float* twi) {
#pragma unroll
    for (int stage = 0; stage < 8; stage++) {
        int half = 1 << stage;
#pragma unroll
        for (int u = 0; u < 4; u++) {
            int b   = lane + 32 * u;          // butterfly id 0..127
            int pos = b & (half - 1);
            int i   = ((b >> stage) << (stage + 1)) + pos;
            int j   = i + half;
            int tm  = pos << (7 - stage);     // twiddle index: pos * (256/len)
            float wr = twr[tm], wi = twi[tm];
            float ar = re[i * RS], ai = im[i * RS];
            float br = re[j * RS], bi = im[j * RS];
            float tr = wr * br - wi * bi;
            float ti = wr * bi + wi * br;
            re[i * RS] = ar + tr;  im[i * RS] = ai + ti;
            re[j * RS] = ar - tr;  im[j * RS] = ai - ti;
        }
        __syncwarp();
    }
}

// Build block-shared twiddle table W^m = exp(DIR * 2*pi*i*m/256), m=0..127
template <int DIR>
__device__ __forceinline__ void build_twiddles(float* twr, float* twi, int tid) {
    if (tid < 128) {
        float th = (float)tid * (6.283185307179586476925f / 256.0f);
        float s, c;
        sincosf(th, &s, &c);
        twr[tid] = c;
        twi[tid] = (DIR < 0) ? -s : s;
    }
}

// ---------------------------------------------------------------------------
// FFT pass along the contiguous axis (axis 2). Warp per line, 8 lines/block.
// ---------------------------------------------------------------------------
template <int DIR>
__global__ void __launch_bounds__(256) fft_axis2(float2* __restrict__ g) {
    __shared__ float s_re[8][256];
    __shared__ float s_im[8][256];
    __shared__ float twr[128], twi[128];

    int tid = threadIdx.x;
    int w = tid >> 5, lane = tid & 31;
    build_twiddles<DIR>(twr, twi, tid);

    int base = (blockIdx.x * 8 + w) * 256;
#pragma unroll
    for (int u = 0; u < 8; u++) {
        int idx = lane + 32 * u;
        float2 v = g[base + idx];
        int r = __brev((unsigned)idx) >> 24;   // 8-bit reversal
        s_re[w][r] = v.x;
        s_im[w][r] = v.y;
    }
    __syncthreads();   // twiddle table + this warp's loads

    warp_fft256<1>(&s_re[w][0], &s_im[w][0], lane, twr, twi);

#pragma unroll
    for (int u = 0; u < 8; u++) {
        int idx = lane + 32 * u;
        float2 v;
        v.x = s_re[w][idx];
        v.y = s_im[w][idx];
        g[base + idx] = v;
    }
}

// ---------------------------------------------------------------------------
// FFT pass along a strided axis. Tile: 256 rows (transform axis, stride S) x
// 8 contiguous columns (fastest axis) -> coalesced 64B segments.
// outerStride: stride of the non-transform, non-contiguous index.
//   axis1 pass: S=256,   outerStride=65536 (outer = i0)
//   axis0 pass: S=65536, outerStride=256   (outer = i1)
// ---------------------------------------------------------------------------
template <int DIR>
__global__ void __launch_bounds__(256) fft_strided(float2* __restrict__ g,
                                                   int S, int outerStride) {
    __shared__ float s_re[256 * 9];
    __shared__ float s_im[256 * 9];
    __shared__ float twr[128], twi[128];

    int tid = threadIdx.x;
    build_twiddles<DIR>(twr, twi, tid);

    int outer = blockIdx.x >> 5;
    int t2    = blockIdx.x & 31;
    int base  = outer * outerStride + t2 * 8;

#pragma unroll
    for (int it = 0; it < 8; it++) {
        int e = it * 256 + tid;
        int r = e >> 3, c = e & 7;
        float2 v = g[base + r * S + c];
        int rb = __brev((unsigned)r) >> 24;
        s_re[rb * 9 + c] = v.x;
        s_im[rb * 9 + c] = v.y;
    }
    __syncthreads();

    int w = tid >> 5, lane = tid & 31;       // warp w owns column c = w
    warp_fft256<9>(s_re + w, s_im + w, lane, twr, twi);
    __syncthreads();

#pragma unroll
    for (int it = 0; it < 8; it++) {
        int e = it * 256 + tid;
        int r = e >> 3, c = e & 7;
        float2 v;
        v.x = s_re[r * 9 + c];
        v.y = s_im[r * 9 + c];
        g[base + r * S + c] = v;
    }
}

// ---------------------------------------------------------------------------
// Spectral combine: unpack N^x,N^y from Z(k)/Z(-k), N^z from W(k); build
// Phi(k) = -i * G * 2pi * (sum_d N^_d w_d) / (Lap + 1e-6), scaled by 1/2^24
// (inverse FFT normalization). Writes Phi into gB.
// ---------------------------------------------------------------------------
__global__ void __launch_bounds__(256) combine_kernel() {
    int idx = blockIdx.x * 256 + threadIdx.x;
    int k2 = idx & 255, k1 = (idx >> 8) & 255, k0 = idx >> 16;
    int n0 = (256 - k0) & 255, n1 = (256 - k1) & 255, n2 = (256 - k2) & 255;
    int nidx = (((n0 << 8) | n1) << 8) | n2;

    float2 Z  = gA[idx];
    float2 Zn = gA[nidx];
    float2 Bz = gB[idx];

    // N^x = (Z(k)+conj(Z(-k)))/2 ; N^y = (Z(k)-conj(Z(-k)))/(2i)
    float Nxr = 0.5f * (Z.x + Zn.x);
    float Nxi = 0.5f * (Z.y - Zn.y);
    float Nyr = 0.5f * (Z.y + Zn.y);
    float Nyi = -0.5f * (Z.x - Zn.x);

    float w0 = (float)(k0 - ((k0 >= 128) ? 256 : 0));
    float w1 = (float)(k1 - ((k1 >= 128) ? 256 : 0));
    float w2 = (float)(k2 - ((k2 >= 128) ? 256 : 0));

    float Dr = Nxr * w0 + Nyr * w1 + Bz.x * w2;
    float Di = Nxi * w0 + Nyi * w1 + Bz.y * w2;

    float s = w0 * w0 + w1 * w1 + w2 * w2;
    float G = expf(s * (-200.0f / 65536.0f));                 // exp(-0.5*(2*SIG*|w|/256)^2)
    float denom = -39.478417604357434f * s + 1e-6f;           // Lap + 1e-6
    float f = (6.283185307179586f * G / denom) * (1.0f / 16777216.0f);

    float2 out;
    out.x = Di * f;      // -i*(Dr+i*Di)*f = (Di - i*Dr)*f
    out.y = -Dr * f;
    if (idx == 0) { out.x = 0.0f; out.y = 0.0f; g_accum = 0.0; }
    gB[idx] = out;
}

// ---------------------------------------------------------------------------
// Trilinear gather of phi (gB.x after inverse FFT) at the input points; sum.
// ---------------------------------------------------------------------------
__global__ void __launch_bounds__(256) interp_kernel(const float* __restrict__ V) {
    int p = blockIdx.x * 256 + threadIdx.x;
    float val = 0.0f;
    if (p < NPTS) {
        float vx = V[3 * p + 0], vy = V[3 * p + 1], vz = V[3 * p + 2];
        int ix0, ix1, iy0, iy1, iz0, iz1;
        float fx, fy, fz;
        corner_setup(vx, ix0, ix1, fx);
        corner_setup(vy, iy0, iy1, fy);
        corner_setup(vz, iz0, iz1, fz);
        float wx[2] = {1.0f - fx, fx};
        float wy[2] = {1.0f - fy, fy};
        float wz[2] = {1.0f - fz, fz};
        int ix[2] = {ix0, ix1}, iy[2] = {iy0, iy1}, iz[2] = {iz0, iz1};
#pragma unroll
        for (int c = 0; c < 8; c++) {
            int b0 = (c >> 2) & 1, b1 = (c >> 1) & 1, b2 = c & 1;
            int lin = (((ix[b0] << 8) | iy[b1]) << 8) | iz[b2];
            val += wx[b0] * wy[b1] * wz[b2] * gB[lin].x;
        }
    }
    __shared__ float red[256];
    red[threadIdx.x] = val;
    __syncthreads();
#pragma unroll
    for (int off = 128; off > 0; off >>= 1) {
        if (threadIdx.x < off) red[threadIdx.x] += red[threadIdx.x + off];
        __syncthreads();
    }
    if (threadIdx.x == 0) atomicAdd(&g_accum, (double)red[0]);
}

// ---------------------------------------------------------------------------
// Final shift + normalize: out = -(phi - mean) * 0.5 / |phi[0,0,0] - mean|
// ---------------------------------------------------------------------------
__global__ void __launch_bounds__(256) final_kernel(float* __restrict__ out) {
    int idx = blockIdx.x * 256 + threadIdx.x;
    float mean = (float)(g_accum * (1.0 / (double)NPTS));
    float f0 = gB[0].x - mean;
    float sc = -0.5f / fabsf(f0);
    out[idx] = (gB[idx].x - mean) * sc;
}

// ---------------------------------------------------------------------------
extern "C" void kernel_launch(void* const* d_in, const int* in_sizes, int n_in,
                              void* d_out, int out_size) {
    const float* V  = (const float*)d_in[0];
    const float* Np = (const float*)d_in[1];
    float* out = (float*)d_out;

    void *pA, *pB;
    cudaGetSymbolAddress(&pA, gA);
    cudaGetSymbolAddress(&pB, gB);
    float2* A = (float2*)pA;
    float2* B = (float2*)pB;

    cudaMemsetAsync(pA, 0, (size_t)NVOX * sizeof(float2));
    cudaMemsetAsync(pB, 0, (size_t)NVOX * sizeof(float2));

    scatter_kernel<<<(NPTS + 255) / 256, 256>>>(V, Np);

    // forward FFT of Z = ras_x + i*ras_y
    fft_axis2<-1><<<8192, 256>>>(A);
    fft_strided<-1><<<8192, 256>>>(A, 256, 65536);    // axis 1
    fft_strided<-1><<<8192, 256>>>(A, 65536, 256);    // axis 0

    // forward FFT of W = ras_z
    fft_axis2<-1><<<8192, 256>>>(B);
    fft_strided<-1><<<8192, 256>>>(B, 256, 65536);
    fft_strided<-1><<<8192, 256>>>(B, 65536, 256);

    combine_kernel<<<65536, 256>>>();

    // inverse FFT of Phi (normalization folded into combine)
    fft_axis2<1><<<8192, 256>>>(B);
    fft_strided<1><<<8192, 256>>>(B, 256, 65536);
    fft_strided<1><<<8192, 256>>>(B, 65536, 256);

    interp_kernel<<<(NPTS + 255) / 256, 256>>>(V);
    final_kernel<<<65536, 256>>>(out);
}

// round 3
// speedup vs baseline: 1.7570x; 1.7570x over previous
#include <cuda_runtime.h>
#include <math.h>

static constexpr int NPTS = 500000;
static constexpr int NVOX = 1 << 24;   // 256^3

__device__ float2 gA[NVOX];   // ras_x + i*ras_y -> Z(k)
__device__ float2 gB[NVOX];   // ras_z -> W(k) -> Phi(k) -> ifft(Phi)
__device__ double g_accum;

// ---------------------------------------------------------------------------
__device__ __forceinline__ void corner_setup(float v, int& i0, int& i1, float& f) {
    float x  = v * 256.0f;
    float fl = floorf(x);
    i0 = (int)fl;
    f  = x - fl;
    i1 = (i0 + 1) & 255;
}

// ---------------------------------------------------------------------------
// 1) trilinear scatter-add
// ---------------------------------------------------------------------------
__global__ void __launch_bounds__(256) scatter_kernel(const float* __restrict__ V,
                                                      const float* __restrict__ N) {
    int p = blockIdx.x * 256 + threadIdx.x;
    if (p >= NPTS) return;
    float vx = V[3 * p + 0], vy = V[3 * p + 1], vz = V[3 * p + 2];
    float nx = N[3 * p + 0], ny = N[3 * p + 1], nz = N[3 * p + 2];

    int ix0, ix1, iy0, iy1, iz0, iz1;
    float fx, fy, fz;
    corner_setup(vx, ix0, ix1, fx);
    corner_setup(vy, iy0, iy1, fy);
    corner_setup(vz, iz0, iz1, fz);

    float wx[2] = {1.0f - fx, fx};
    float wy[2] = {1.0f - fy, fy};
    float wz[2] = {1.0f - fz, fz};
    int ix[2] = {ix0, ix1}, iy[2] = {iy0, iy1}, iz[2] = {iz0, iz1};

#pragma unroll
    for (int c = 0; c < 8; c++) {
        int b0 = (c >> 2) & 1, b1 = (c >> 1) & 1, b2 = c & 1;
        int lin = (((ix[b0] << 8) | iy[b1]) << 8) | iz[b2];
        float w = wx[b0] * wy[b1] * wz[b2];
        atomicAdd(&gA[lin].x, w * nx);
        atomicAdd(&gA[lin].y, w * ny);
        atomicAdd(&gB[lin].x, w * nz);
    }
}

// ---------------------------------------------------------------------------
// Warp-level 256-pt FFT: 8 complex per thread.
// In-thread 8-pt DIT (input must be loaded bit-reversed over n1, i.e. reg j
// holds x[32*br3(j) + lane]) -> W_256^{lane*k1} twiddle -> cross-lane 32-pt
// DIF via shfl_xor. Output: lane holds X[k1 + 8*br5(lane)], k1 = reg index.
// ---------------------------------------------------------------------------
__device__ __forceinline__ void xstage(float (&ar)[8], float (&ai)[8], int lane, int h,
                                       float twr_in, float twi_in) {
    const bool up = (lane & h) != 0;
    const float s  = up ? -1.0f : 1.0f;
    const float tr = up ? twr_in : 1.0f;
    const float ti = up ? twi_in : 0.0f;
#pragma unroll
    for (int k = 0; k < 8; k++) {
        float orr = __shfl_xor_sync(0xffffffffu, ar[k], h);
        float ori = __shfl_xor_sync(0xffffffffu, ai[k], h);
        float dr = fmaf(s, ar[k], orr);
        float di = fmaf(s, ai[k], ori);
        ar[k] = dr * tr - di * ti;
        ai[k] = dr * ti + di * tr;
    }
}

template <int DIR>
__device__ __forceinline__ void warp_fft256_reg(float (&ar)[8], float (&ai)[8], int lane) {
    const float D = (float)DIR;
    const float C = 0.70710678118654752440f;
    float tr, ti;

    // 8-pt DIT, stage 0 (tw = 1)
#pragma unroll
    for (int p = 0; p < 8; p += 2) {
        tr = ar[p + 1]; ti = ai[p + 1];
        ar[p + 1] = ar[p] - tr;  ai[p + 1] = ai[p] - ti;
        ar[p] += tr;             ai[p] += ti;
    }
    // stage 1 (tw = 1, (0,D))
#pragma unroll
    for (int q = 0; q < 8; q += 4) {
        tr = ar[q + 2]; ti = ai[q + 2];
        ar[q + 2] = ar[q] - tr;  ai[q + 2] = ai[q] - ti;
        ar[q] += tr;             ai[q] += ti;
        tr = -D * ai[q + 3];     ti = D * ar[q + 3];
        ar[q + 3] = ar[q + 1] - tr;  ai[q + 3] = ai[q + 1] - ti;
        ar[q + 1] += tr;             ai[q + 1] += ti;
    }
    // stage 2 (tw = 1, (C,DC), (0,D), (-C,DC))
    tr = ar[4]; ti = ai[4];
    ar[4] = ar[0] - tr; ai[4] = ai[0] - ti; ar[0] += tr; ai[0] += ti;
    tr = C * (ar[5] - D * ai[5]); ti = C * (ai[5] + D * ar[5]);
    ar[5] = ar[1] - tr; ai[5] = ai[1] - ti; ar[1] += tr; ai[1] += ti;
    tr = -D * ai[6]; ti = D * ar[6];
    ar[6] = ar[2] - tr; ai[6] = ai[2] - ti; ar[2] += tr; ai[2] += ti;
    tr = -C * (ar[7] + D * ai[7]); ti = C * (D * ar[7] - ai[7]);
    ar[7] = ar[3] - tr; ai[7] = ai[3] - ti; ar[3] += tr; ai[3] += ti;

    // twiddle by W_256^{lane*k1}
    float w1r, w1i;
    __sincosf(D * 0.024543692606170259f * (float)lane, &w1i, &w1r);   // 2*pi/256
    float wr = w1r, wi = w1i;
#pragma unroll
    for (int k = 1; k < 8; k++) {
        tr = ar[k] * wr - ai[k] * wi;
        ai[k] = ar[k] * wi + ai[k] * wr;
        ar[k] = tr;
        if (k < 7) { float nr = wr * w1r - wi * w1i; wi = wr * w1i + wi * w1r; wr = nr; }
    }

    // cross-lane 32-pt DIF over lanes
    float s16r, s16i, s8r, s8i, s4r, s4i;
    __sincosf(D * 0.19634954084936207f * (float)(lane & 15), &s16i, &s16r);  // pi/16
    __sincosf(D * 0.39269908169872414f * (float)(lane & 7),  &s8i,  &s8r);   // pi/8
    __sincosf(D * 0.78539816339744831f * (float)(lane & 3),  &s4i,  &s4r);   // pi/4
    xstage(ar, ai, lane, 16, s16r, s16i);
    xstage(ar, ai, lane, 8,  s8r,  s8i);
    xstage(ar, ai, lane, 4,  s4r,  s4i);
    xstage(ar, ai, lane, 2, (lane & 1) ? 0.0f : 1.0f, (lane & 1) ? D : 0.0f);
    xstage(ar, ai, lane, 1, 1.0f, 0.0f);
}

// ---------------------------------------------------------------------------
// FFT pass along contiguous axis (axis 2). Warp per line, no shared memory.
// In-place safe: every lane's stores are after the last shfl_xor_sync, which
// no lane reaches before all lanes' loads (data-dependence convergence).
// ---------------------------------------------------------------------------
template <int DIR>
__global__ void __launch_bounds__(256) fft_axis2_reg(float2* __restrict__ g) {
    int w = threadIdx.x >> 5, lane = threadIdx.x & 31;
    int base = (blockIdx.x * 8 + w) * 256;

    float ar[8], ai[8];
    const int br3[8] = {0, 4, 2, 6, 1, 5, 3, 7};
#pragma unroll
    for (int j = 0; j < 8; j++) {
        float2 v = g[base + 32 * br3[j] + lane];
        ar[j] = v.x; ai[j] = v.y;
    }

    warp_fft256_reg<DIR>(ar, ai, lane);

    int ob = base + 8 * (int)(__brev((unsigned)lane) >> 27);
    float4* o = (float4*)(g + ob);
    o[0] = make_float4(ar[0], ai[0], ar[1], ai[1]);
    o[1] = make_float4(ar[2], ai[2], ar[3], ai[3]);
    o[2] = make_float4(ar[4], ai[4], ar[5], ai[5]);
    o[3] = make_float4(ar[6], ai[6], ar[7], ai[7]);
}

// ---------------------------------------------------------------------------
// FFT pass along a strided axis. Smem used only as a transpose tile:
// 256 rows (transform axis, stride S) x 8 contiguous cols.
// Layout addr = 9r + (c ^ ((r>>5)&7)):
//   - column read (r = 32*n1+lane): conflict-free (stride-9, xor const/instr)
//   - register write (r = k1+8*br5(lane), c = w): conflict-free (proved: bank
//     bits 3-4 from 8*(k2&3), bits 0-2 xored by k2>>2 -> injective in k2)
//   - linear copy phases: <=2-way on 3 of 32 banks
// ---------------------------------------------------------------------------
template <int DIR>
__global__ void __launch_bounds__(256) fft_strided_reg(float2* __restrict__ g,
                                                       int S, int outerStride) {
    __shared__ float s_re[2304];
    __shared__ float s_im[2304];

    int tid  = threadIdx.x;
    int outer = blockIdx.x >> 5;
    int t2    = blockIdx.x & 31;
    int base  = outer * outerStride + t2 * 8;

#pragma unroll
    for (int it = 0; it < 8; it++) {
        int e = it * 256 + tid;
        int r = e >> 3, c = e & 7;
        float2 v = g[base + r * S + c];
        int a = 9 * r + (c ^ ((r >> 5) & 7));
        s_re[a] = v.x; s_im[a] = v.y;
    }
    __syncthreads();

    int w = tid >> 5, lane = tid & 31;
    float ar[8], ai[8];
    const int br3[8] = {0, 4, 2, 6, 1, 5, 3, 7};
#pragma unroll
    for (int j = 0; j < 8; j++) {
        int r = 32 * br3[j] + lane;
        int a = 9 * r + (w ^ ((r >> 5) & 7));
        ar[j] = s_re[a]; ai[j] = s_im[a];
    }

    warp_fft256_reg<DIR>(ar, ai, lane);
    __syncthreads();   // all column reads done before results overwrite tile

    int k2 = (int)(__brev((unsigned)lane) >> 27);
#pragma unroll
    for (int k1 = 0; k1 < 8; k1++) {
        int r = k1 + 8 * k2;
        int a = 9 * r + (w ^ ((r >> 5) & 7));
        s_re[a] = ar[k1]; s_im[a] = ai[k1];
    }
    __syncthreads();

#pragma unroll
    for (int it = 0; it < 8; it++) {
        int e = it * 256 + tid;
        int r = e >> 3, c = e & 7;
        int a = 9 * r + (c ^ ((r >> 5) & 7));
        float2 v;
        v.x = s_re[a]; v.y = s_im[a];
        g[base + r * S + c] = v;
    }
}

// ---------------------------------------------------------------------------
// Spectral combine (unchanged).
// ---------------------------------------------------------------------------
__global__ void __launch_bounds__(256) combine_kernel() {
    int idx = blockIdx.x * 256 + threadIdx.x;
    int k2 = idx & 255, k1 = (idx >> 8) & 255, k0 = idx >> 16;
    int n0 = (256 - k0) & 255, n1 = (256 - k1) & 255, n2 = (256 - k2) & 255;
    int nidx = (((n0 << 8) | n1) << 8) | n2;

    float2 Z  = gA[idx];
    float2 Zn = gA[nidx];
    float2 Bz = gB[idx];

    float Nxr = 0.5f * (Z.x + Zn.x);
    float Nxi = 0.5f * (Z.y - Zn.y);
    float Nyr = 0.5f * (Z.y + Zn.y);
    float Nyi = -0.5f * (Z.x - Zn.x);

    float w0 = (float)(k0 - ((k0 >= 128) ? 256 : 0));
    float w1 = (float)(k1 - ((k1 >= 128) ? 256 : 0));
    float w2 = (float)(k2 - ((k2 >= 128) ? 256 : 0));

    float Dr = Nxr * w0 + Nyr * w1 + Bz.x * w2;
    float Di = Nxi * w0 + Nyi * w1 + Bz.y * w2;

    float s = w0 * w0 + w1 * w1 + w2 * w2;
    float G = expf(s * (-200.0f / 65536.0f));
    float denom = -39.478417604357434f * s + 1e-6f;
    float f = (6.283185307179586f * G / denom) * (1.0f / 16777216.0f);

    float2 out;
    out.x = Di * f;
    out.y = -Dr * f;
    if (idx == 0) { out.x = 0.0f; out.y = 0.0f; g_accum = 0.0; }
    gB[idx] = out;
}

// ---------------------------------------------------------------------------
__global__ void __launch_bounds__(256) interp_kernel(const float* __restrict__ V) {
    int p = blockIdx.x * 256 + threadIdx.x;
    float val = 0.0f;
    if (p < NPTS) {
        float vx = V[3 * p + 0], vy = V[3 * p + 1], vz = V[3 * p + 2];
        int ix0, ix1, iy0, iy1, iz0, iz1;
        float fx, fy, fz;
        corner_setup(vx, ix0, ix1, fx);
        corner_setup(vy, iy0, iy1, fy);
        corner_setup(vz, iz0, iz1, fz);
        float wx[2] = {1.0f - fx, fx};
        float wy[2] = {1.0f - fy, fy};
        float wz[2] = {1.0f - fz, fz};
        int ix[2] = {ix0, ix1}, iy[2] = {iy0, iy1}, iz[2] = {iz0, iz1};
#pragma unroll
        for (int c = 0; c < 8; c++) {
            int b0 = (c >> 2) & 1, b1 = (c >> 1) & 1, b2 = c & 1;
            int lin = (((ix[b0] << 8) | iy[b1]) << 8) | iz[b2];
            val += wx[b0] * wy[b1] * wz[b2] * gB[lin].x;
        }
    }
    __shared__ float red[256];
    red[threadIdx.x] = val;
    __syncthreads();
#pragma unroll
    for (int off = 128; off > 0; off >>= 1) {
        if (threadIdx.x < off) red[threadIdx.x] += red[threadIdx.x + off];
        __syncthreads();
    }
    if (threadIdx.x == 0) atomicAdd(&g_accum, (double)red[0]);
}

// ---------------------------------------------------------------------------
__global__ void __launch_bounds__(256) final_kernel(float* __restrict__ out) {
    int idx = blockIdx.x * 256 + threadIdx.x;
    float mean = (float)(g_accum * (1.0 / (double)NPTS));
    float f0 = gB[0].x - mean;
    float sc = -0.5f / fabsf(f0);
    out[idx] = (gB[idx].x - mean) * sc;
}

// ---------------------------------------------------------------------------
extern "C" void kernel_launch(void* const* d_in, const int* in_sizes, int n_in,
                              void* d_out, int out_size) {
    const float* V  = (const float*)d_in[0];
    const float* Np = (const float*)d_in[1];
    float* out = (float*)d_out;

    void *pA, *pB;
    cudaGetSymbolAddress(&pA, gA);
    cudaGetSymbolAddress(&pB, gB);
    float2* A = (float2*)pA;
    float2* B = (float2*)pB;

    cudaMemsetAsync(pA, 0, (size_t)NVOX * sizeof(float2));
    cudaMemsetAsync(pB, 0, (size_t)NVOX * sizeof(float2));

    scatter_kernel<<<(NPTS + 255) / 256, 256>>>(V, Np);

    // forward FFT of Z = ras_x + i*ras_y
    fft_axis2_reg<-1><<<8192, 256>>>(A);
    fft_strided_reg<-1><<<8192, 256>>>(A, 256, 65536);    // axis 1
    fft_strided_reg<-1><<<8192, 256>>>(A, 65536, 256);    // axis 0

    // forward FFT of W = ras_z
    fft_axis2_reg<-1><<<8192, 256>>>(B);
    fft_strided_reg<-1><<<8192, 256>>>(B, 256, 65536);
    fft_strided_reg<-1><<<8192, 256>>>(B, 65536, 256);

    combine_kernel<<<65536, 256>>>();

    // inverse FFT of Phi
    fft_axis2_reg<1><<<8192, 256>>>(B);
    fft_strided_reg<1><<<8192, 256>>>(B, 256, 65536);
    fft_strided_reg<1><<<8192, 256>>>(B, 65536, 256);

    interp_kernel<<<(NPTS + 255) / 256, 256>>>(V);
    final_kernel<<<65536, 256>>>(out);
}

// round 5
// speedup vs baseline: 1.9060x; 1.0848x over previous
#include <cuda_runtime.h>
#include <math.h>

static constexpr int NPTS = 500000;
static constexpr int NVOX = 1 << 24;   // 256^3

__device__ float2 gA[NVOX];   // ras_x + i*ras_y -> Z(k)
__device__ float2 gB[NVOX];   // W(k)=N^_z -> (fused) Phi partial -> spatial phi (complex mid-passes)
__device__ float  gZ[NVOX];   // ras_z (real) on the way in; phi (real) on the way out
__device__ double g_accum;

// ---------------------------------------------------------------------------
__device__ __forceinline__ void corner_setup(float v, int& i0, int& i1, float& f) {
    float x  = v * 256.0f;
    float fl = floorf(x);
    i0 = (int)fl;
    f  = x - fl;
    i1 = (i0 + 1) & 255;
}

// ---------------------------------------------------------------------------
// 1) trilinear scatter-add: (nx,ny) -> gA via vec2 reduction, nz -> gZ scalar
// ---------------------------------------------------------------------------
__global__ void __launch_bounds__(256) scatter_kernel(const float* __restrict__ V,
                                                      const float* __restrict__ N) {
    int p = blockIdx.x * 256 + threadIdx.x;
    if (p >= NPTS) return;
    float vx = V[3 * p + 0], vy = V[3 * p + 1], vz = V[3 * p + 2];
    float nx = N[3 * p + 0], ny = N[3 * p + 1], nz = N[3 * p + 2];

    int ix0, ix1, iy0, iy1, iz0, iz1;
    float fx, fy, fz;
    corner_setup(vx, ix0, ix1, fx);
    corner_setup(vy, iy0, iy1, fy);
    corner_setup(vz, iz0, iz1, fz);

    float wx[2] = {1.0f - fx, fx};
    float wy[2] = {1.0f - fy, fy};
    float wz[2] = {1.0f - fz, fz};
    int ix[2] = {ix0, ix1}, iy[2] = {iy0, iy1}, iz[2] = {iz0, iz1};

#pragma unroll
    for (int c = 0; c < 8; c++) {
        int b0 = (c >> 2) & 1, b1 = (c >> 1) & 1, b2 = c & 1;
        int lin = (((ix[b0] << 8) | iy[b1]) << 8) | iz[b2];
        float w = wx[b0] * wy[b1] * wz[b2];
        asm volatile("red.global.add.v2.f32 [%0], {%1, %2};"
                     :: "l"(&gA[lin]), "f"(w * nx), "f"(w * ny) : "memory");
        atomicAdd(&gZ[lin], w * nz);
    }
}

// ---------------------------------------------------------------------------
// Warp-level 256-pt FFT: 8 complex per thread (see round-2 derivation).
// Input loaded bit-reversed over n1 (reg j holds x[32*br3(j)+lane]);
// output: lane holds X[k1 + 8*br5(lane)], k1 = reg index.
// ---------------------------------------------------------------------------
__device__ __forceinline__ void xstage(float (&ar)[8], float (&ai)[8], int lane, int h,
                                       float twr_in, float twi_in) {
    const bool up = (lane & h) != 0;
    const float s  = up ? -1.0f : 1.0f;
    const float tr = up ? twr_in : 1.0f;
    const float ti = up ? twi_in : 0.0f;
#pragma unroll
    for (int k = 0; k < 8; k++) {
        float orr = __shfl_xor_sync(0xffffffffu, ar[k], h);
        float ori = __shfl_xor_sync(0xffffffffu, ai[k], h);
        float dr = fmaf(s, ar[k], orr);
        float di = fmaf(s, ai[k], ori);
        ar[k] = dr * tr - di * ti;
        ai[k] = dr * ti + di * tr;
    }
}

template <int DIR>
__device__ __forceinline__ void warp_fft256_reg(float (&ar)[8], float (&ai)[8], int lane) {
    const float D = (float)DIR;
    const float C = 0.70710678118654752440f;
    float tr, ti;

#pragma unroll
    for (int p = 0; p < 8; p += 2) {
        tr = ar[p + 1]; ti = ai[p + 1];
        ar[p + 1] = ar[p] - tr;  ai[p + 1] = ai[p] - ti;
        ar[p] += tr;             ai[p] += ti;
    }
#pragma unroll
    for (int q = 0; q < 8; q += 4) {
        tr = ar[q + 2]; ti = ai[q + 2];
        ar[q + 2] = ar[q] - tr;  ai[q + 2] = ai[q] - ti;
        ar[q] += tr;             ai[q] += ti;
        tr = -D * ai[q + 3];     ti = D * ar[q + 3];
        ar[q + 3] = ar[q + 1] - tr;  ai[q + 3] = ai[q + 1] - ti;
        ar[q + 1] += tr;             ai[q + 1] += ti;
    }
    tr = ar[4]; ti = ai[4];
    ar[4] = ar[0] - tr; ai[4] = ai[0] - ti; ar[0] += tr; ai[0] += ti;
    tr = C * (ar[5] - D * ai[5]); ti = C * (ai[5] + D * ar[5]);
    ar[5] = ar[1] - tr; ai[5] = ai[1] - ti; ar[1] += tr; ai[1] += ti;
    tr = -D * ai[6]; ti = D * ar[6];
    ar[6] = ar[2] - tr; ai[6] = ai[2] - ti; ar[2] += tr; ai[2] += ti;
    tr = -C * (ar[7] + D * ai[7]); ti = C * (D * ar[7] - ai[7]);
    ar[7] = ar[3] - tr; ai[7] = ai[3] - ti; ar[3] += tr; ai[3] += ti;

    float w1r, w1i;
    __sincosf(D * 0.024543692606170259f * (float)lane, &w1i, &w1r);   // 2*pi/256
    float wr = w1r, wi = w1i;
#pragma unroll
    for (int k = 1; k < 8; k++) {
        tr = ar[k] * wr - ai[k] * wi;
        ai[k] = ar[k] * wi + ai[k] * wr;
        ar[k] = tr;
        if (k < 7) { float nr = wr * w1r - wi * w1i; wi = wr * w1i + wi * w1r; wr = nr; }
    }

    float s16r, s16i, s8r, s8i, s4r, s4i;
    __sincosf(D * 0.19634954084936207f * (float)(lane & 15), &s16i, &s16r);  // pi/16
    __sincosf(D * 0.39269908169872414f * (float)(lane & 7),  &s8i,  &s8r);   // pi/8
    __sincosf(D * 0.78539816339744831f * (float)(lane & 3),  &s4i,  &s4r);   // pi/4
    xstage(ar, ai, lane, 16, s16r, s16i);
    xstage(ar, ai, lane, 8,  s8r,  s8i);
    xstage(ar, ai, lane, 4,  s4r,  s4i);
    xstage(ar, ai, lane, 2, (lane & 1) ? 0.0f : 1.0f, (lane & 1) ? D : 0.0f);
    xstage(ar, ai, lane, 1, 1.0f, 0.0f);
}

// ---------------------------------------------------------------------------
// axis-2 pass, complex in/out (used for the A volume forward pass)
// ---------------------------------------------------------------------------
template <int DIR>
__global__ void __launch_bounds__(256) fft_axis2_reg(float2* __restrict__ g) {
    int w = threadIdx.x >> 5, lane = threadIdx.x & 31;
    int base = (blockIdx.x * 8 + w) * 256;

    float ar[8], ai[8];
    const int br3[8] = {0, 4, 2, 6, 1, 5, 3, 7};
#pragma unroll
    for (int j = 0; j < 8; j++) {
        float2 v = g[base + 32 * br3[j] + lane];
        ar[j] = v.x; ai[j] = v.y;
    }
    warp_fft256_reg<DIR>(ar, ai, lane);
    int ob = base + 8 * (int)(__brev((unsigned)lane) >> 27);
    float4* o = (float4*)(g + ob);
    o[0] = make_float4(ar[0], ai[0], ar[1], ai[1]);
    o[1] = make_float4(ar[2], ai[2], ar[3], ai[3]);
    o[2] = make_float4(ar[4], ai[4], ar[5], ai[5]);
    o[3] = make_float4(ar[6], ai[6], ar[7], ai[7]);
}

// axis-2 forward pass with REAL input (z channel): gZ -> gB
__global__ void __launch_bounds__(256) fft_axis2_fromreal(const float* __restrict__ in,
                                                          float2* __restrict__ g) {
    int w = threadIdx.x >> 5, lane = threadIdx.x & 31;
    int base = (blockIdx.x * 8 + w) * 256;

    float ar[8], ai[8];
    const int br3[8] = {0, 4, 2, 6, 1, 5, 3, 7};
#pragma unroll
    for (int j = 0; j < 8; j++) {
        ar[j] = in[base + 32 * br3[j] + lane];
        ai[j] = 0.0f;
    }
    warp_fft256_reg<-1>(ar, ai, lane);
    int ob = base + 8 * (int)(__brev((unsigned)lane) >> 27);
    float4* o = (float4*)(g + ob);
    o[0] = make_float4(ar[0], ai[0], ar[1], ai[1]);
    o[1] = make_float4(ar[2], ai[2], ar[3], ai[3]);
    o[2] = make_float4(ar[4], ai[4], ar[5], ai[5]);
    o[3] = make_float4(ar[6], ai[6], ar[7], ai[7]);
}

// axis-2 inverse pass writing only the REAL part: gB -> gZ
__global__ void __launch_bounds__(256) fft_axis2_toreal(const float2* __restrict__ g,
                                                        float* __restrict__ outr) {
    int w = threadIdx.x >> 5, lane = threadIdx.x & 31;
    int base = (blockIdx.x * 8 + w) * 256;

    float ar[8], ai[8];
    const int br3[8] = {0, 4, 2, 6, 1, 5, 3, 7};
#pragma unroll
    for (int j = 0; j < 8; j++) {
        float2 v = g[base + 32 * br3[j] + lane];
        ar[j] = v.x; ai[j] = v.y;
    }
    warp_fft256_reg<1>(ar, ai, lane);
    int ob = base + 8 * (int)(__brev((unsigned)lane) >> 27);
    float4* o = (float4*)(outr + ob);
    o[0] = make_float4(ar[0], ar[1], ar[2], ar[3]);
    o[1] = make_float4(ar[4], ar[5], ar[6], ar[7]);
}

// ---------------------------------------------------------------------------
// Strided-axis pass (transpose tile in smem; layout addr = 9r + (c ^ ((r>>5)&7))
// proven conflict-free for the register phases, <=2-way for copy phases).
// ---------------------------------------------------------------------------
template <int DIR>
__global__ void __launch_bounds__(256) fft_strided_reg(float2* __restrict__ g,
                                                       int S, int outerStride) {
    __shared__ float s_re[2304];
    __shared__ float s_im[2304];

    int tid  = threadIdx.x;
    int outer = blockIdx.x >> 5;
    int t2    = blockIdx.x & 31;
    int base  = outer * outerStride + t2 * 8;

#pragma unroll
    for (int it = 0; it < 8; it++) {
        int e = it * 256 + tid;
        int r = e >> 3, c = e & 7;
        float2 v = g[base + r * S + c];
        int a = 9 * r + (c ^ ((r >> 5) & 7));
        s_re[a] = v.x; s_im[a] = v.y;
    }
    __syncthreads();

    int w = tid >> 5, lane = tid & 31;
    float ar[8], ai[8];
    const int br3[8] = {0, 4, 2, 6, 1, 5, 3, 7};
#pragma unroll
    for (int j = 0; j < 8; j++) {
        int r = 32 * br3[j] + lane;
        int a = 9 * r + (w ^ ((r >> 5) & 7));
        ar[j] = s_re[a]; ai[j] = s_im[a];
    }

    warp_fft256_reg<DIR>(ar, ai, lane);
    __syncthreads();

    int k2 = (int)(__brev((unsigned)lane) >> 27);
#pragma unroll
    for (int k1 = 0; k1 < 8; k1++) {
        int r = k1 + 8 * k2;
        int a = 9 * r + (w ^ ((r >> 5) & 7));
        s_re[a] = ar[k1]; s_im[a] = ai[k1];
    }
    __syncthreads();

#pragma unroll
    for (int it = 0; it < 8; it++) {
        int e = it * 256 + tid;
        int r = e >> 3, c = e & 7;
        int a = 9 * r + (c ^ ((r >> 5) & 7));
        float2 v;
        v.x = s_re[a]; v.y = s_im[a];
        g[base + r * S + c] = v;
    }
}

// ---------------------------------------------------------------------------
// FUSED: spectral combine + inverse FFT along axis 0.
// Tile covers k0 = 0..255 (rows), fixed k1 = outer, k2 in [8*t2, 8*t2+8).
// Per element builds Phi(k) from Z(k)=gA[k], Z(-k)=gA[-k], W(k)=gB[k], then
// transforms along k0 and writes the result (in-place tile) to gB.
// ---------------------------------------------------------------------------
__global__ void __launch_bounds__(256) fft_inv0_combine() {
    __shared__ float s_re[2304];
    __shared__ float s_im[2304];

    int tid   = threadIdx.x;
    int outer = blockIdx.x >> 5;     // k1
    int t2    = blockIdx.x & 31;     // k2 chunk
    int base  = outer * 256 + t2 * 8;

    int k1 = outer;
    int n1 = (256 - k1) & 255;
    float w1 = (float)(k1 - ((k1 >= 128) ? 256 : 0));

#pragma unroll
    for (int it = 0; it < 8; it++) {
        int e = it * 256 + tid;
        int r = e >> 3, c = e & 7;
        int k0 = r, k2 = t2 * 8 + c;
        int idx  = (k0 << 16) | base | c;
        int n0 = (256 - k0) & 255, n2 = (256 - k2) & 255;
        int nidx = (n0 << 16) | (n1 << 8) | n2;

        float2 Z  = gA[idx];
        float2 Zn = gA[nidx];
        float2 Bz = gB[idx];

        float Nxr = 0.5f * (Z.x + Zn.x);
        float Nxi = 0.5f * (Z.y - Zn.y);
        float Nyr = 0.5f * (Z.y + Zn.y);
        float Nyi = -0.5f * (Z.x - Zn.x);

        float w0 = (float)(k0 - ((k0 >= 128) ? 256 : 0));
        float w2 = (float)(k2 - ((k2 >= 128) ? 256 : 0));

        float Dr = Nxr * w0 + Nyr * w1 + Bz.x * w2;
        float Di = Nxi * w0 + Nyi * w1 + Bz.y * w2;

        float s = w0 * w0 + w1 * w1 + w2 * w2;
        float G = expf(s * (-200.0f / 65536.0f));
        float denom = -39.478417604357434f * s + 1e-6f;
        float f = (6.283185307179586f * G / denom) * (1.0f / 16777216.0f);

        float pr = Di * f;
        float pi = -Dr * f;
        if (idx == 0) { pr = 0.0f; pi = 0.0f; }

        int a = 9 * r + (c ^ ((r >> 5) & 7));
        s_re[a] = pr; s_im[a] = pi;
    }
    __syncthreads();

    int w = tid >> 5, lane = tid & 31;
    float ar[8], ai[8];
    const int br3[8] = {0, 4, 2, 6, 1, 5, 3, 7};
#pragma unroll
    for (int j = 0; j < 8; j++) {
        int r = 32 * br3[j] + lane;
        int a = 9 * r + (w ^ ((r >> 5) & 7));
        ar[j] = s_re[a]; ai[j] = s_im[a];
    }

    warp_fft256_reg<1>(ar, ai, lane);
    __syncthreads();

    int k2r = (int)(__brev((unsigned)lane) >> 27);
#pragma unroll
    for (int k = 0; k < 8; k++) {
        int r = k + 8 * k2r;
        int a = 9 * r + (w ^ ((r >> 5) & 7));
        s_re[a] = ar[k]; s_im[a] = ai[k];
    }
    __syncthreads();

#pragma unroll
    for (int it = 0; it < 8; it++) {
        int e = it * 256 + tid;
        int r = e >> 3, c = e & 7;
        int a = 9 * r + (c ^ ((r >> 5) & 7));
        float2 v;
        v.x = s_re[a]; v.y = s_im[a];
        gB[(r << 16) | base | c] = v;
    }
}

// ---------------------------------------------------------------------------
__global__ void __launch_bounds__(256) interp_kernel(const float* __restrict__ V) {
    int p = blockIdx.x * 256 + threadIdx.x;
    float val = 0.0f;
    if (p < NPTS) {
        float vx = V[3 * p + 0], vy = V[3 * p + 1], vz = V[3 * p + 2];
        int ix0, ix1, iy0, iy1, iz0, iz1;
        float fx, fy, fz;
        corner_setup(vx, ix0, ix1, fx);
        corner_setup(vy, iy0, iy1, fy);
        corner_setup(vz, iz0, iz1, fz);
        float wx[2] = {1.0f - fx, fx};
        float wy[2] = {1.0f - fy, fy};
        float wz[2] = {1.0f - fz, fz};
        int ix[2] = {ix0, ix1}, iy[2] = {iy0, iy1}, iz[2] = {iz0, iz1};
#pragma unroll
        for (int c = 0; c < 8; c++) {
            int b0 = (c >> 2) & 1, b1 = (c >> 1) & 1, b2 = c & 1;
            int lin = (((ix[b0] << 8) | iy[b1]) << 8) | iz[b2];
            val += wx[b0] * wy[b1] * wz[b2] * gZ[lin];
        }
    }
    __shared__ float red[256];
    red[threadIdx.x] = val;
    __syncthreads();
#pragma unroll
    for (int off = 128; off > 0; off >>= 1) {
        if (threadIdx.x < off) red[threadIdx.x] += red[threadIdx.x + off];
        __syncthreads();
    }
    if (threadIdx.x == 0) atomicAdd(&g_accum, (double)red[0]);
}

// ---------------------------------------------------------------------------
__global__ void __launch_bounds__(256) final_kernel(float* __restrict__ out) {
    int idx = blockIdx.x * 256 + threadIdx.x;
    float mean = (float)(g_accum * (1.0 / (double)NPTS));
    float f0 = gZ[0] - mean;
    float sc = -0.5f / fabsf(f0);
    out[idx] = (gZ[idx] - mean) * sc;
}

// ---------------------------------------------------------------------------
extern "C" void kernel_launch(void* const* d_in, const int* in_sizes, int n_in,
                              void* d_out, int out_size) {
    const float* V  = (const float*)d_in[0];
    const float* Np = (const float*)d_in[1];
    float* out = (float*)d_out;

    void *pA, *pB, *pZ, *pAcc;
    cudaGetSymbolAddress(&pA, gA);
    cudaGetSymbolAddress(&pB, gB);
    cudaGetSymbolAddress(&pZ, gZ);
    cudaGetSymbolAddress(&pAcc, g_accum);
    float2* A = (float2*)pA;
    float2* B = (float2*)pB;

    cudaMemsetAsync(pA, 0, (size_t)NVOX * sizeof(float2));
    cudaMemsetAsync(pZ, 0, (size_t)NVOX * sizeof(float));
    cudaMemsetAsync(pAcc, 0, sizeof(double));

    scatter_kernel<<<(NPTS + 255) / 256, 256>>>(V, Np);

    // forward FFT of Z = ras_x + i*ras_y
    fft_axis2_reg<-1><<<8192, 256>>>(A);
    fft_strided_reg<-1><<<8192, 256>>>(A, 256, 65536);    // axis 1
    fft_strided_reg<-1><<<8192, 256>>>(A, 65536, 256);    // axis 0

    // forward FFT of W = ras_z (real input)
    fft_axis2_fromreal<<<8192, 256>>>((const float*)pZ, B);
    fft_strided_reg<-1><<<8192, 256>>>(B, 256, 65536);
    fft_strided_reg<-1><<<8192, 256>>>(B, 65536, 256);

    // inverse FFT of Phi: combine fused into axis-0 pass, then axis1, axis2
    fft_inv0_combine<<<8192, 256>>>();
    fft_strided_reg<1><<<8192, 256>>>(B, 256, 65536);     // axis 1
    fft_axis2_toreal<<<8192, 256>>>(B, (float*)pZ);       // axis 2, real out

    interp_kernel<<<(NPTS + 255) / 256, 256>>>(V);
    final_kernel<<<65536, 256>>>(out);
}

// round 7
// speedup vs baseline: 2.4278x; 1.2738x over previous
#include <cuda_runtime.h>
#include <math.h>

static constexpr int NPTS = 500000;
static constexpr int NVOX = 1 << 24;   // 256^3
static constexpr int NCHUNK_HALF = 17; // k2 chunks covering 0..135 (need 0..128)

__device__ float2 gA[NVOX];   // ras_x + i*ras_y -> Z(k)
__device__ float2 gB[NVOX];   // W(k) (k2<=135) -> Phi partial -> spatial phi
__device__ float  gZ[NVOX];   // ras_z (real) in; phi (real) out
__device__ double g_accum;

// ---------------------------------------------------------------------------
__device__ __forceinline__ void corner_setup(float v, int& i0, int& i1, float& f) {
    float x  = v * 256.0f;
    float fl = floorf(x);
    i0 = (int)fl;
    f  = x - fl;
    i1 = (i0 + 1) & 255;
}

// ---------------------------------------------------------------------------
__global__ void __launch_bounds__(256) scatter_kernel(const float* __restrict__ V,
                                                      const float* __restrict__ N) {
    int p = blockIdx.x * 256 + threadIdx.x;
    if (p >= NPTS) return;
    float vx = V[3 * p + 0], vy = V[3 * p + 1], vz = V[3 * p + 2];
    float nx = N[3 * p + 0], ny = N[3 * p + 1], nz = N[3 * p + 2];

    int ix0, ix1, iy0, iy1, iz0, iz1;
    float fx, fy, fz;
    corner_setup(vx, ix0, ix1, fx);
    corner_setup(vy, iy0, iy1, fy);
    corner_setup(vz, iz0, iz1, fz);

    float wx[2] = {1.0f - fx, fx};
    float wy[2] = {1.0f - fy, fy};
    float wz[2] = {1.0f - fz, fz};
    int ix[2] = {ix0, ix1}, iy[2] = {iy0, iy1}, iz[2] = {iz0, iz1};

#pragma unroll
    for (int c = 0; c < 8; c++) {
        int b0 = (c >> 2) & 1, b1 = (c >> 1) & 1, b2 = c & 1;
        int lin = (((ix[b0] << 8) | iy[b1]) << 8) | iz[b2];
        float w = wx[b0] * wy[b1] * wz[b2];
        asm volatile("red.global.add.v2.f32 [%0], {%1, %2};"
                     :: "l"(&gA[lin]), "f"(w * nx), "f"(w * ny) : "memory");
        atomicAdd(&gZ[lin], w * nz);
    }
}

// ---------------------------------------------------------------------------
// Warp-level 256-pt FFT: 8 complex per thread.
// Input: reg j holds x[32*br3(j)+lane]. Output: lane holds X[k1+8*br5(lane)].
// ---------------------------------------------------------------------------
__device__ __forceinline__ void xstage(float (&ar)[8], float (&ai)[8], int lane, int h,
                                       float twr_in, float twi_in) {
    const bool up = (lane & h) != 0;
    const float s  = up ? -1.0f : 1.0f;
    const float tr = up ? twr_in : 1.0f;
    const float ti = up ? twi_in : 0.0f;
#pragma unroll
    for (int k = 0; k < 8; k++) {
        float orr = __shfl_xor_sync(0xffffffffu, ar[k], h);
        float ori = __shfl_xor_sync(0xffffffffu, ai[k], h);
        float dr = fmaf(s, ar[k], orr);
        float di = fmaf(s, ai[k], ori);
        ar[k] = dr * tr - di * ti;
        ai[k] = dr * ti + di * tr;
    }
}

template <int DIR>
__device__ __forceinline__ void warp_fft256_reg(float (&ar)[8], float (&ai)[8], int lane) {
    const float D = (float)DIR;
    const float C = 0.70710678118654752440f;
    float tr, ti;

#pragma unroll
    for (int p = 0; p < 8; p += 2) {
        tr = ar[p + 1]; ti = ai[p + 1];
        ar[p + 1] = ar[p] - tr;  ai[p + 1] = ai[p] - ti;
        ar[p] += tr;             ai[p] += ti;
    }
#pragma unroll
    for (int q = 0; q < 8; q += 4) {
        tr = ar[q + 2]; ti = ai[q + 2];
        ar[q + 2] = ar[q] - tr;  ai[q + 2] = ai[q] - ti;
        ar[q] += tr;             ai[q] += ti;
        tr = -D * ai[q + 3];     ti = D * ar[q + 3];
        ar[q + 3] = ar[q + 1] - tr;  ai[q + 3] = ai[q + 1] - ti;
        ar[q + 1] += tr;             ai[q + 1] += ti;
    }
    tr = ar[4]; ti = ai[4];
    ar[4] = ar[0] - tr; ai[4] = ai[0] - ti; ar[0] += tr; ai[0] += ti;
    tr = C * (ar[5] - D * ai[5]); ti = C * (ai[5] + D * ar[5]);
    ar[5] = ar[1] - tr; ai[5] = ai[1] - ti; ar[1] += tr; ai[1] += ti;
    tr = -D * ai[6]; ti = D * ar[6];
    ar[6] = ar[2] - tr; ai[6] = ai[2] - ti; ar[2] += tr; ai[2] += ti;
    tr = -C * (ar[7] + D * ai[7]); ti = C * (D * ar[7] - ai[7]);
    ar[7] = ar[3] - tr; ai[7] = ai[3] - ti; ar[3] += tr; ai[3] += ti;

    float w1r, w1i;
    __sincosf(D * 0.024543692606170259f * (float)lane, &w1i, &w1r);   // 2*pi/256
    float wr = w1r, wi = w1i;
#pragma unroll
    for (int k = 1; k < 8; k++) {
        tr = ar[k] * wr - ai[k] * wi;
        ai[k] = ar[k] * wi + ai[k] * wr;
        ar[k] = tr;
        if (k < 7) { float nr = wr * w1r - wi * w1i; wi = wr * w1i + wi * w1r; wr = nr; }
    }

    float s16r, s16i, s8r, s8i, s4r, s4i;
    __sincosf(D * 0.19634954084936207f * (float)(lane & 15), &s16i, &s16r);  // pi/16
    __sincosf(D * 0.39269908169872414f * (float)(lane & 7),  &s8i,  &s8r);   // pi/8
    __sincosf(D * 0.78539816339744831f * (float)(lane & 3),  &s4i,  &s4r);   // pi/4
    xstage(ar, ai, lane, 16, s16r, s16i);
    xstage(ar, ai, lane, 8,  s8r,  s8i);
    xstage(ar, ai, lane, 4,  s4r,  s4i);
    xstage(ar, ai, lane, 2, (lane & 1) ? 0.0f : 1.0f, (lane & 1) ? D : 0.0f);
    xstage(ar, ai, lane, 1, 1.0f, 0.0f);
}

// smem address map for a 256-entry line: addr(k) = 9*(k>>3) + (k&7)
__device__ __forceinline__ int lmap(int k) { return 9 * (k >> 3) + (k & 7); }

// ---------------------------------------------------------------------------
// axis-2 complex pass (A volume forward), warp per line.
// ---------------------------------------------------------------------------
template <int DIR>
__global__ void __launch_bounds__(256) fft_axis2_reg(float2* __restrict__ g) {
    int w = threadIdx.x >> 5, lane = threadIdx.x & 31;
    int base = (blockIdx.x * 8 + w) * 256;

    float ar[8], ai[8];
    const int br3[8] = {0, 4, 2, 6, 1, 5, 3, 7};
#pragma unroll
    for (int j = 0; j < 8; j++) {
        float2 v = g[base + 32 * br3[j] + lane];
        ar[j] = v.x; ai[j] = v.y;
    }
    warp_fft256_reg<DIR>(ar, ai, lane);
    int ob = base + 8 * (int)(__brev((unsigned)lane) >> 27);
    float4* o = (float4*)(g + ob);
    o[0] = make_float4(ar[0], ai[0], ar[1], ai[1]);
    o[1] = make_float4(ar[2], ai[2], ar[3], ai[3]);
    o[2] = make_float4(ar[4], ai[4], ar[5], ai[5]);
    o[3] = make_float4(ar[6], ai[6], ar[7], ai[7]);
}

// ---------------------------------------------------------------------------
// axis-2 forward R2C: two real lines (i1=2j, 2j+1) packed as one complex FFT;
// unpack Hermitian halves, write k2 in [0..135] only.
// ---------------------------------------------------------------------------
__global__ void __launch_bounds__(256) fft_axis2_r2c(const float* __restrict__ in,
                                                     float2* __restrict__ g) {
    __shared__ float s_re[8][288];
    __shared__ float s_im[8][288];
    int w = threadIdx.x >> 5, lane = threadIdx.x & 31;
    int pj = blockIdx.x * 8 + w;           // pair index
    int i0 = pj >> 7, j = pj & 127;
    int base_a = (i0 << 16) | (j << 9);    // line i1 = 2j
    int base_b = base_a + 256;             // line i1 = 2j+1

    float ar[8], ai[8];
    const int br3[8] = {0, 4, 2, 6, 1, 5, 3, 7};
#pragma unroll
    for (int t = 0; t < 8; t++) {
        int idx = 32 * br3[t] + lane;
        ar[t] = in[base_a + idx];
        ai[t] = in[base_b + idx];
    }
    warp_fft256_reg<-1>(ar, ai, lane);

    int m = (int)(__brev((unsigned)lane) >> 27);
#pragma unroll
    for (int t = 0; t < 8; t++) {          // addr = 9m + t : conflict-free
        s_re[w][9 * m + t] = ar[t];
        s_im[w][9 * m + t] = ai[t];
    }
    __syncwarp();

#pragma unroll
    for (int t = 0; t < 5; t++) {
        int k = lane + 32 * t;             // t=4 -> k in [128..135] for lanes 0..7
        if (t < 4 || lane < 8) {
            int km = (256 - k) & 255;
            float ur = s_re[w][lmap(k)],  ui = s_im[w][lmap(k)];
            float vr = s_re[w][lmap(km)], vi = s_im[w][lmap(km)];
            g[base_a + k] = make_float2(0.5f * (ur + vr),  0.5f * (ui - vi));
            g[base_b + k] = make_float2(0.5f * (ui + vi), -0.5f * (ur - vr));
        }
    }
}

// ---------------------------------------------------------------------------
// axis-2 inverse C2R: two Hermitian lines -> one complex inverse FFT -> two
// real lines. Reads bins k2 in [0..128]; writes real phi into gZ.
// ---------------------------------------------------------------------------
__global__ void __launch_bounds__(256) fft_axis2_c2r(const float2* __restrict__ g,
                                                     float* __restrict__ outr) {
    __shared__ float s_re[8][288];
    __shared__ float s_im[8][288];
    int w = threadIdx.x >> 5, lane = threadIdx.x & 31;
    int pj = blockIdx.x * 8 + w;
    int i0 = pj >> 7, j = pj & 127;
    int base_a = (i0 << 16) | (j << 9);
    int base_b = base_a + 256;

#pragma unroll
    for (int t = 0; t < 5; t++) {
        int k = lane + 32 * t;
        if (t < 4 || lane == 0) {          // k <= 128
            float2 Ha = g[base_a + k];
            float2 Hb = g[base_b + k];
            // P[k] = Ha + i*Hb
            s_re[w][lmap(k)] = Ha.x - Hb.y;
            s_im[w][lmap(k)] = Ha.y + Hb.x;
            if (k >= 1 && k <= 127) {
                // P[256-k] = conj(Ha) + i*conj(Hb)
                s_re[w][lmap(256 - k)] = Ha.x + Hb.y;
                s_im[w][lmap(256 - k)] = Hb.x - Ha.y;
            }
        }
    }
    __syncwarp();

    float ar[8], ai[8];
    const int br3[8] = {0, 4, 2, 6, 1, 5, 3, 7};
#pragma unroll
    for (int t = 0; t < 8; t++) {
        int idx = 32 * br3[t] + lane;
        ar[t] = s_re[w][lmap(idx)];
        ai[t] = s_im[w][lmap(idx)];
    }
    warp_fft256_reg<1>(ar, ai, lane);

    int ob = 8 * (int)(__brev((unsigned)lane) >> 27);
    float4* oa = (float4*)(outr + base_a + ob);
    float4* obp = (float4*)(outr + base_b + ob);
    oa[0]  = make_float4(ar[0], ar[1], ar[2], ar[3]);
    oa[1]  = make_float4(ar[4], ar[5], ar[6], ar[7]);
    obp[0] = make_float4(ai[0], ai[1], ai[2], ai[3]);
    obp[1] = make_float4(ai[4], ai[5], ai[6], ai[7]);
}

// ---------------------------------------------------------------------------
// Strided-axis pass. 2D grid: blockIdx.y = outer, blockIdx.x = k2 chunk.
// ---------------------------------------------------------------------------
template <int DIR>
__global__ void __launch_bounds__(256) fft_strided_reg(float2* __restrict__ g,
                                                       int S, int outerStride) {
    __shared__ float s_re[2304];
    __shared__ float s_im[2304];

    int tid  = threadIdx.x;
    int base = blockIdx.y * outerStride + blockIdx.x * 8;

#pragma unroll
    for (int it = 0; it < 8; it++) {
        int e = it * 256 + tid;
        int r = e >> 3, c = e & 7;
        float2 v = g[base + r * S + c];
        int a = 9 * r + (c ^ ((r >> 5) & 7));
        s_re[a] = v.x; s_im[a] = v.y;
    }
    __syncthreads();

    int w = tid >> 5, lane = tid & 31;
    float ar[8], ai[8];
    const int br3[8] = {0, 4, 2, 6, 1, 5, 3, 7};
#pragma unroll
    for (int j = 0; j < 8; j++) {
        int r = 32 * br3[j] + lane;
        int a = 9 * r + (w ^ ((r >> 5) & 7));
        ar[j] = s_re[a]; ai[j] = s_im[a];
    }

    warp_fft256_reg<DIR>(ar, ai, lane);
    __syncthreads();

    int k2 = (int)(__brev((unsigned)lane) >> 27);
#pragma unroll
    for (int k1 = 0; k1 < 8; k1++) {
        int r = k1 + 8 * k2;
        int a = 9 * r + (w ^ ((r >> 5) & 7));
        s_re[a] = ar[k1]; s_im[a] = ai[k1];
    }
    __syncthreads();

#pragma unroll
    for (int it = 0; it < 8; it++) {
        int e = it * 256 + tid;
        int r = e >> 3, c = e & 7;
        int a = 9 * r + (c ^ ((r >> 5) & 7));
        float2 v;
        v.x = s_re[a]; v.y = s_im[a];
        g[base + r * S + c] = v;
    }
}

// ---------------------------------------------------------------------------
// FUSED spectral combine + inverse axis-0 pass. blockIdx.y = k1,
// blockIdx.x = k2 chunk (0..16, covering k2 0..135; only 0..128 used later).
// ---------------------------------------------------------------------------
__global__ void __launch_bounds__(256) fft_inv0_combine() {
    __shared__ float s_re[2304];
    __shared__ float s_im[2304];

    int tid  = threadIdx.x;
    int k1   = blockIdx.y;
    int t2   = blockIdx.x;
    int base = k1 * 256 + t2 * 8;

    int n1 = (256 - k1) & 255;
    float w1 = (float)(k1 - ((k1 >= 128) ? 256 : 0));

#pragma unroll
    for (int it = 0; it < 8; it++) {
        int e = it * 256 + tid;
        int r = e >> 3, c = e & 7;
        int k0 = r, k2 = t2 * 8 + c;
        int idx  = (k0 << 16) | base | c;
        int n0 = (256 - k0) & 255, n2 = (256 - k2) & 255;
        int nidx = (n0 << 16) | (n1 << 8) | n2;

        float2 Z  = gA[idx];
        float2 Zn = gA[nidx];
        float2 Bz = gB[idx];

        float Nxr = 0.5f * (Z.x + Zn.x);
        float Nxi = 0.5f * (Z.y - Zn.y);
        float Nyr = 0.5f * (Z.y + Zn.y);
        float Nyi = -0.5f * (Z.x - Zn.x);

        float w0 = (float)(k0 - ((k0 >= 128) ? 256 : 0));
        float w2 = (float)(k2 - ((k2 >= 128) ? 256 : 0));

        float Dr = Nxr * w0 + Nyr * w1 + Bz.x * w2;
        float Di = Nxi * w0 + Nyi * w1 + Bz.y * w2;

        float s = w0 * w0 + w1 * w1 + w2 * w2;
        float G = expf(s * (-200.0f / 65536.0f));
        float denom = -39.478417604357434f * s + 1e-6f;
        float f = (6.283185307179586f * G / denom) * (1.0f / 16777216.0f);

        float pr = Di * f;
        float pi = -Dr * f;
        if (idx == 0) { pr = 0.0f; pi = 0.0f; }

        int a = 9 * r + (c ^ ((r >> 5) & 7));
        s_re[a] = pr; s_im[a] = pi;
    }
    __syncthreads();

    int w = tid >> 5, lane = tid & 31;
    float ar[8], ai[8];
    const int br3[8] = {0, 4, 2, 6, 1, 5, 3, 7};
#pragma unroll
    for (int j = 0; j < 8; j++) {
        int r = 32 * br3[j] + lane;
        int a = 9 * r + (w ^ ((r >> 5) & 7));
        ar[j] = s_re[a]; ai[j] = s_im[a];
    }

    warp_fft256_reg<1>(ar, ai, lane);
    __syncthreads();

    int k2r = (int)(__brev((unsigned)lane) >> 27);
#pragma unroll
    for (int k = 0; k < 8; k++) {
        int r = k + 8 * k2r;
        int a = 9 * r + (w ^ ((r >> 5) & 7));
        s_re[a] = ar[k]; s_im[a] = ai[k];
    }
    __syncthreads();

#pragma unroll
    for (int it = 0; it < 8; it++) {
        int e = it * 256 + tid;
        int r = e >> 3, c = e & 7;
        int a = 9 * r + (c ^ ((r >> 5) & 7));
        float2 v;
        v.x = s_re[a]; v.y = s_im[a];
        gB[(r << 16) | base | c] = v;
    }
}

// ---------------------------------------------------------------------------
__global__ void __launch_bounds__(256) interp_kernel(const float* __restrict__ V) {
    int p = blockIdx.x * 256 + threadIdx.x;
    float val = 0.0f;
    if (p < NPTS) {
        float vx = V[3 * p + 0], vy = V[3 * p + 1], vz = V[3 * p + 2];
        int ix0, ix1, iy0, iy1, iz0, iz1;
        float fx, fy, fz;
        corner_setup(vx, ix0, ix1, fx);
        corner_setup(vy, iy0, iy1, fy);
        corner_setup(vz, iz0, iz1, fz);
        float wx[2] = {1.0f - fx, fx};
        float wy[2] = {1.0f - fy, fy};
        float wz[2] = {1.0f - fz, fz};
        int ix[2] = {ix0, ix1}, iy[2] = {iy0, iy1}, iz[2] = {iz0, iz1};
#pragma unroll
        for (int c = 0; c < 8; c++) {
            int b0 = (c >> 2) & 1, b1 = (c >> 1) & 1, b2 = c & 1;
            int lin = (((ix[b0] << 8) | iy[b1]) << 8) | iz[b2];
            val += wx[b0] * wy[b1] * wz[b2] * gZ[lin];
        }
    }
    __shared__ float red[256];
    red[threadIdx.x] = val;
    __syncthreads();
#pragma unroll
    for (int off = 128; off > 0; off >>= 1) {
        if (threadIdx.x < off) red[threadIdx.x] += red[threadIdx.x + off];
        __syncthreads();
    }
    if (threadIdx.x == 0) atomicAdd(&g_accum, (double)red[0]);
}

// ---------------------------------------------------------------------------
__global__ void __launch_bounds__(256) final_kernel(float* __restrict__ out) {
    int idx = blockIdx.x * 256 + threadIdx.x;
    float mean = (float)(g_accum * (1.0 / (double)NPTS));
    float f0 = gZ[0] - mean;
    float sc = -0.5f / fabsf(f0);
    out[idx] = (gZ[idx] - mean) * sc;
}

// ---------------------------------------------------------------------------
extern "C" void kernel_launch(void* const* d_in, const int* in_sizes, int n_in,
                              void* d_out, int out_size) {
    const float* V  = (const float*)d_in[0];
    const float* Np = (const float*)d_in[1];
    float* out = (float*)d_out;

    void *pA, *pB, *pZ, *pAcc;
    cudaGetSymbolAddress(&pA, gA);
    cudaGetSymbolAddress(&pB, gB);
    cudaGetSymbolAddress(&pZ, gZ);
    cudaGetSymbolAddress(&pAcc, g_accum);
    float2* A = (float2*)pA;
    float2* B = (float2*)pB;

    cudaMemsetAsync(pA, 0, (size_t)NVOX * sizeof(float2));
    cudaMemsetAsync(pZ, 0, (size_t)NVOX * sizeof(float));
    cudaMemsetAsync(pAcc, 0, sizeof(double));

    scatter_kernel<<<(NPTS + 255) / 256, 256>>>(V, Np);

    dim3 gFull(32, 256);
    dim3 gHalf(NCHUNK_HALF, 256);

    // forward FFT of Z = ras_x + i*ras_y (full complex volume)
    fft_axis2_reg<-1><<<8192, 256>>>(A);
    fft_strided_reg<-1><<<gFull, 256>>>(A, 256, 65536);    // axis 1
    fft_strided_reg<-1><<<gFull, 256>>>(A, 65536, 256);    // axis 0

    // forward FFT of W = ras_z (real input, Hermitian half-volume k2<=135)
    fft_axis2_r2c<<<4096, 256>>>((const float*)pZ, B);
    fft_strided_reg<-1><<<gHalf, 256>>>(B, 256, 65536);    // axis 1 (half chunks)
    fft_strided_reg<-1><<<gHalf, 256>>>(B, 65536, 256);    // axis 0 (half chunks)

    // inverse: fused combine + axis0 (half), axis1 (half), axis2 C2R
    fft_inv0_combine<<<gHalf, 256>>>();
    fft_strided_reg<1><<<gHalf, 256>>>(B, 256, 65536);     // axis 1 (half chunks)
    fft_axis2_c2r<<<4096, 256>>>(B, (float*)pZ);           // axis 2, real out

    interp_kernel<<<(NPTS + 255) / 256, 256>>>(V);
    final_kernel<<<65536, 256>>>(out);
}